// round 6
// baseline (speedup 1.0000x reference)
#include <cuda_runtime.h>

// PathGuidedAggregator:
//   out[i,:] = (deg[i] <= 5) ? (sum_{e: rows[e]==i} embeds[cols[e],:]) / max(count_i,1) : 0
// Inputs int32 (JAX x64 disabled). rows SORTED.
// R5: worklist compaction of sparse rows + persistent fixed-grid main kernel
// (phase 1: zero dense rows; phase 2: process sparse rows from worklist).

#define EMBED_DIM 128
#define SPARSE_THRESHOLD 5
#define MAX_ENT 100000
#define GRID_MAIN 1184   // 148 SMs x 8 resident 128-thread blocks

__device__ int g_start[MAX_ENT];
__device__ int g_end[MAX_ENT];
__device__ int g_work[MAX_ENT];
__device__ int g_nwork;

__global__ void reset_kernel() { g_nwork = 0; }

// Init CSR ptrs + build compacted worklist of sparse rows.
__global__ void prep_kernel(const int* __restrict__ degrees, int n_ent) {
    int i = blockIdx.x * blockDim.x + threadIdx.x;
    if (i >= n_ent) return;
    g_start[i] = 0;
    g_end[i] = 0;
    if (__ldg(&degrees[i]) <= SPARSE_THRESHOLD) {
        int pos = atomicAdd(&g_nwork, 1);
        g_work[pos] = i;
    }
}

// Boundary scatter over sorted rows: first/last occurrence of each row value.
__global__ void boundaries_kernel(const int* __restrict__ rows, int n_edges) {
    int e = blockIdx.x * blockDim.x + threadIdx.x;
    if (e >= n_edges) return;
    int r = __ldg(&rows[e]);
    if (e == 0 || __ldg(&rows[e - 1]) != r) g_start[r] = e;
    if (e == n_edges - 1 || __ldg(&rows[e + 1]) != r) g_end[r] = e + 1;
}

__global__ void __launch_bounds__(EMBED_DIM)
main_kernel(const float* __restrict__ embeds,
            const int* __restrict__ degrees,
            const int* __restrict__ cols,
            float* __restrict__ out,
            int n_ent) {
    const int d = threadIdx.x;

    // ---- Phase 1: zero-fill DENSE rows (vectorized, coalesced). ----
    // 32 float4 per row of 128 floats.
    {
        const int tid = blockIdx.x * EMBED_DIM + d;
        const int n_vec = n_ent * (EMBED_DIM / 4);
        const float4 z = make_float4(0.f, 0.f, 0.f, 0.f);
        float4* out4 = (float4*)out;
        for (int v = tid; v < n_vec; v += GRID_MAIN * EMBED_DIM) {
            const int row = v >> 5;
            if (__ldg(&degrees[row]) > SPARSE_THRESHOLD) out4[v] = z;
        }
    }

    // ---- Phase 2: sparse rows from compacted worklist (disjoint from phase 1 rows). ----
    const int nwork = g_nwork;
    __shared__ int s_cols[EMBED_DIM];

    for (int w = blockIdx.x; w < nwork; w += GRID_MAIN) {
        const int row = g_work[w];
        const int start = g_start[row];
        const int end   = g_end[row];

        float a0 = 0.f, a1 = 0.f, a2 = 0.f, a3 = 0.f;
        float a4 = 0.f, a5 = 0.f, a6 = 0.f, a7 = 0.f;

        for (int base = start; base < end; base += EMBED_DIM) {
            const int m = min(EMBED_DIM, end - base);
            if (d < m) s_cols[d] = __ldg(&cols[base + d]);
            __syncthreads();

            int k = 0;
            for (; k + 7 < m; k += 8) {
                int c0 = s_cols[k + 0], c1 = s_cols[k + 1];
                int c2 = s_cols[k + 2], c3 = s_cols[k + 3];
                int c4 = s_cols[k + 4], c5 = s_cols[k + 5];
                int c6 = s_cols[k + 6], c7 = s_cols[k + 7];
                a0 += __ldg(&embeds[(size_t)c0 * EMBED_DIM + d]);
                a1 += __ldg(&embeds[(size_t)c1 * EMBED_DIM + d]);
                a2 += __ldg(&embeds[(size_t)c2 * EMBED_DIM + d]);
                a3 += __ldg(&embeds[(size_t)c3 * EMBED_DIM + d]);
                a4 += __ldg(&embeds[(size_t)c4 * EMBED_DIM + d]);
                a5 += __ldg(&embeds[(size_t)c5 * EMBED_DIM + d]);
                a6 += __ldg(&embeds[(size_t)c6 * EMBED_DIM + d]);
                a7 += __ldg(&embeds[(size_t)c7 * EMBED_DIM + d]);
            }
            for (; k < m; ++k) {
                int c = s_cols[k];
                a0 += __ldg(&embeds[(size_t)c * EMBED_DIM + d]);
            }
            __syncthreads();
        }

        const float acc = ((a0 + a1) + (a2 + a3)) + ((a4 + a5) + (a6 + a7));
        const int cnt = end - start;
        const float inv = 1.0f / (float)(cnt > 0 ? cnt : 1);
        out[(size_t)row * EMBED_DIM + d] = acc * inv;
    }
}

extern "C" void kernel_launch(void* const* d_in, const int* in_sizes, int n_in,
                              void* d_out, int out_size) {
    const float* embeds  = (const float*)d_in[0];  // [N_ENT, 128] fp32
    const int*   degrees = (const int*)d_in[1];    // [N_ENT] int32
    const int*   rows    = (const int*)d_in[2];    // [N_EDGES] int32, sorted
    const int*   cols    = (const int*)d_in[3];    // [N_EDGES] int32
    float*       out     = (float*)d_out;          // [N_ENT, 128] fp32

    const int n_ent   = in_sizes[1];
    const int n_edges = in_sizes[2];

    reset_kernel<<<1, 1>>>();
    prep_kernel<<<(n_ent + 255) / 256, 256>>>(degrees, n_ent);
    boundaries_kernel<<<(n_edges + 255) / 256, 256>>>(rows, n_edges);
    main_kernel<<<GRID_MAIN, EMBED_DIM>>>(embeds, degrees, cols, out, n_ent);
}

// round 8
// speedup vs baseline: 1.3108x; 1.3108x over previous
#include <cuda_runtime.h>

// PathGuidedAggregator:
//   out[i,:] = (deg[i] <= 5) ? (sum_{e: rows[e]==i} embeds[cols[e],:]) / max(count_i,1) : 0
// Inputs int32 (JAX x64 disabled). rows SORTED.
// R6 design (resubmit after broker timeout): warp-per-row with float4 lanes
// (32 lanes x 16B = full 128-dim row), shfl-broadcast columns (no smem or
// syncthreads), dense rows = 1 STG.128 zero write per lane. CSR boundary
// kernel only (g_start/g_end zero-init'd device globals; zero-edge rows stay
// (0,0); rewrites are idempotent across graph replays).

#define EMBED_DIM 128
#define SPARSE_THRESHOLD 5
#define MAX_ENT 100000
#define WARPS_PER_BLOCK 8
#define BLOCK_THREADS (WARPS_PER_BLOCK * 32)

__device__ int g_start[MAX_ENT];  // zero-initialized at module load
__device__ int g_end[MAX_ENT];

// Boundary scatter over sorted rows: first/last occurrence of each row value.
__global__ void boundaries_kernel(const int* __restrict__ rows, int n_edges) {
    int e = blockIdx.x * blockDim.x + threadIdx.x;
    if (e >= n_edges) return;
    int r = __ldg(&rows[e]);
    if (e == 0 || __ldg(&rows[e - 1]) != r) g_start[r] = e;
    if (e == n_edges - 1 || __ldg(&rows[e + 1]) != r) g_end[r] = e + 1;
}

__global__ void __launch_bounds__(BLOCK_THREADS)
main_kernel(const float* __restrict__ embeds,
            const int* __restrict__ degrees,
            const int* __restrict__ cols,
            float* __restrict__ out,
            int n_ent) {
    const int row  = blockIdx.x * WARPS_PER_BLOCK + (threadIdx.x >> 5);
    const int lane = threadIdx.x & 31;
    if (row >= n_ent) return;

    float4* out4 = (float4*)(out + (size_t)row * EMBED_DIM) + lane;

    // Dense row: one vectorized zero write by the warp, done.
    if (__ldg(&degrees[row]) > SPARSE_THRESHOLD) {
        *out4 = make_float4(0.f, 0.f, 0.f, 0.f);
        return;
    }

    const int start = __ldg(&g_start[row]);
    const int end   = __ldg(&g_end[row]);

    float4 a0 = make_float4(0.f, 0.f, 0.f, 0.f);
    float4 a1 = make_float4(0.f, 0.f, 0.f, 0.f);
    float4 a2 = make_float4(0.f, 0.f, 0.f, 0.f);
    float4 a3 = make_float4(0.f, 0.f, 0.f, 0.f);

    for (int base = start; base < end; base += 32) {
        const int m = min(32, end - base);
        // One coalesced col load covers up to 32 edges; broadcast via shfl.
        const int mycol = (lane < m) ? __ldg(&cols[base + lane]) : 0;

        int e = 0;
        for (; e + 3 < m; e += 4) {
            const int c0 = __shfl_sync(0xffffffffu, mycol, e + 0);
            const int c1 = __shfl_sync(0xffffffffu, mycol, e + 1);
            const int c2 = __shfl_sync(0xffffffffu, mycol, e + 2);
            const int c3 = __shfl_sync(0xffffffffu, mycol, e + 3);
            const float4 v0 = __ldg((const float4*)(embeds + (size_t)c0 * EMBED_DIM) + lane);
            const float4 v1 = __ldg((const float4*)(embeds + (size_t)c1 * EMBED_DIM) + lane);
            const float4 v2 = __ldg((const float4*)(embeds + (size_t)c2 * EMBED_DIM) + lane);
            const float4 v3 = __ldg((const float4*)(embeds + (size_t)c3 * EMBED_DIM) + lane);
            a0.x += v0.x; a0.y += v0.y; a0.z += v0.z; a0.w += v0.w;
            a1.x += v1.x; a1.y += v1.y; a1.z += v1.z; a1.w += v1.w;
            a2.x += v2.x; a2.y += v2.y; a2.z += v2.z; a2.w += v2.w;
            a3.x += v3.x; a3.y += v3.y; a3.z += v3.z; a3.w += v3.w;
        }
        for (; e < m; ++e) {
            const int c = __shfl_sync(0xffffffffu, mycol, e);
            const float4 v = __ldg((const float4*)(embeds + (size_t)c * EMBED_DIM) + lane);
            a0.x += v.x; a0.y += v.y; a0.z += v.z; a0.w += v.w;
        }
    }

    float4 acc;
    acc.x = (a0.x + a1.x) + (a2.x + a3.x);
    acc.y = (a0.y + a1.y) + (a2.y + a3.y);
    acc.z = (a0.z + a1.z) + (a2.z + a3.z);
    acc.w = (a0.w + a1.w) + (a2.w + a3.w);

    const int cnt = end - start;
    const float inv = 1.0f / (float)(cnt > 0 ? cnt : 1);
    acc.x *= inv; acc.y *= inv; acc.z *= inv; acc.w *= inv;
    *out4 = acc;
}

extern "C" void kernel_launch(void* const* d_in, const int* in_sizes, int n_in,
                              void* d_out, int out_size) {
    const float* embeds  = (const float*)d_in[0];  // [N_ENT, 128] fp32
    const int*   degrees = (const int*)d_in[1];    // [N_ENT] int32
    const int*   rows    = (const int*)d_in[2];    // [N_EDGES] int32, sorted
    const int*   cols    = (const int*)d_in[3];    // [N_EDGES] int32
    float*       out     = (float*)d_out;          // [N_ENT, 128] fp32

    const int n_ent   = in_sizes[1];
    const int n_edges = in_sizes[2];

    boundaries_kernel<<<(n_edges + 255) / 256, 256>>>(rows, n_edges);
    main_kernel<<<(n_ent + WARPS_PER_BLOCK - 1) / WARPS_PER_BLOCK, BLOCK_THREADS>>>(
        embeds, degrees, cols, out, n_ent);
}